// round 4
// baseline (speedup 1.0000x reference)
#include <cuda_runtime.h>
#include <cstddef>

typedef unsigned long long ull;

__device__ __forceinline__ ull ffma2(ull a, ull b, ull c) {
    ull d;
    asm("fma.rn.f32x2 %0, %1, %2, %3;" : "=l"(d) : "l"(a), "l"(b), "l"(c));
    return d;
}
__device__ __forceinline__ ull splat2(float f) {
    ull d;
    asm("mov.b64 %0, {%1, %1};" : "=l"(d) : "f"(f));
    return d;
}
__device__ __forceinline__ float lo32(ull v) { return __uint_as_float((unsigned)v); }
__device__ __forceinline__ float hi32(ull v) { return __uint_as_float((unsigned)(v >> 32)); }

#define B_    256
#define IN_   2048
#define NC_   1000
#define O_    4096
#define H_    4
#define NDEC  (O_ * H_)   // 16384
#define NEG_SLOPE 0.1f

#define BM 128
#define BN 128
#define BK 16

#define FSPLIT 16
__device__ float fc_scratch[FSPLIT * B_ * NC_];

// Inner product over one smem ktile.
//   As: plain [m][k]  (A read = broadcast LDS.32, splat via MOV)
//   Bs: plain [k][n]  (B read = natural f32x2 pairs, conflict-free LDS.128)
//   acc[r][j]: r = m row (ty*8+r); j: n = tx*4+{0,1},{2,3} / 64+tx*4+{0,1},{2,3}
#define INNER_LOOP(AsT, BsT, acc, tx, ty)                                     \
    _Pragma("unroll")                                                         \
    for (int k = 0; k < BK; k++) {                                            \
        ull a[8];                                                             \
        _Pragma("unroll")                                                     \
        for (int r = 0; r < 8; r++) a[r] = splat2(AsT[ty * 8 + r][k]);        \
        ulonglong2 b0 = *(const ulonglong2*)&BsT[k][tx * 4];                  \
        ulonglong2 b1 = *(const ulonglong2*)&BsT[k][64 + tx * 4];             \
        ull bv[4] = {b0.x, b0.y, b1.x, b1.y};                                 \
        _Pragma("unroll")                                                     \
        for (int r = 0; r < 8; r++) {                                         \
            _Pragma("unroll")                                                 \
            for (int j = 0; j < 4; j++)                                       \
                acc[r][j] = ffma2(a[r], bv[j], acc[r][j]);                    \
        }                                                                     \
    }

// ---------------------------------------------------------------------------
// Decoder: C[256,16384] = X @ W1r, epilogue bias+leaky+collapse -> [256,4096]
// ---------------------------------------------------------------------------
__global__ __launch_bounds__(256, 2)
void decoder_kernel(const float* __restrict__ x, const float* __restrict__ W1,
                    const float* __restrict__ b1, const float* __restrict__ W2,
                    const float* __restrict__ b2, float* __restrict__ out2)
{
    __shared__ float As[2][BM][BK];
    __shared__ float Bs[2][BK][BN];

    const int tid = threadIdx.x;
    const int tx = tid & 15;
    const int ty = tid >> 4;
    const int m0 = blockIdx.y * BM;
    const int n0 = blockIdx.x * BN;

    ull acc[8][4];
    #pragma unroll
    for (int r = 0; r < 8; r++)
        #pragma unroll
        for (int j = 0; j < 4; j++) acc[r][j] = 0ull;

    const int ar = tid >> 2;              // 0..63
    const int ac = (tid & 3) * 4;         // k offset (float4)
    const int o_l = tid & 31;             // decoder within tile
    const int e   = tid >> 5;             // 8-float chunk index
    const float* w1p = W1 + (size_t)(n0 / 4 + o_l) * (IN_ * H_) + e * 8;
    const float* xa0 = x + (size_t)(m0 + ar) * IN_ + ac;
    const float* xa1 = x + (size_t)(m0 + ar + 64) * IN_ + ac;

    const int NT = IN_ / BK;              // 128 ktiles

    // Prologue: tile 0 -> buf 0
    {
        float4 pa0 = *(const float4*)(xa0);
        float4 pa1 = *(const float4*)(xa1);
        float4 pb0 = *(const float4*)(w1p);
        float4 pb1 = *(const float4*)(w1p + 4);
        *(float4*)&As[0][ar][ac]          = pa0;
        *(float4*)&As[0][ar + 64][ac]     = pa1;
        *(float4*)&Bs[0][2 * e][o_l * 4]     = pb0;
        *(float4*)&Bs[0][2 * e + 1][o_l * 4] = pb1;
    }
    __syncthreads();

    for (int kt = 0; kt < NT; kt++) {
        const int buf = kt & 1;
        float4 pa0, pa1, pb0, pb1;
        if (kt + 1 < NT) {
            const int k0 = (kt + 1) * BK;
            pa0 = *(const float4*)(xa0 + k0);
            pa1 = *(const float4*)(xa1 + k0);
            const float* p0 = w1p + (size_t)k0 * H_;
            pb0 = *(const float4*)(p0);
            pb1 = *(const float4*)(p0 + 4);
        }
        INNER_LOOP(As[buf], Bs[buf], acc, tx, ty)
        if (kt + 1 < NT) {
            const int nb = buf ^ 1;
            *(float4*)&As[nb][ar][ac]          = pa0;
            *(float4*)&As[nb][ar + 64][ac]     = pa1;
            *(float4*)&Bs[nb][2 * e][o_l * 4]     = pb0;
            *(float4*)&Bs[nb][2 * e + 1][o_l * 4] = pb1;
        }
        __syncthreads();
    }

    // Epilogue: each thread owns 2 full decoders
    const int gn0 = n0 + tx * 4;
    const int gn1 = gn0 + 64;
    const int d0 = gn0 >> 2, d1 = gn1 >> 2;
    float b1a[4], w2a[4], b1b[4], w2b[4];
    #pragma unroll
    for (int h = 0; h < 4; h++) {
        b1a[h] = b1[gn0 + h]; w2a[h] = W2[gn0 + h];
        b1b[h] = b1[gn1 + h]; w2b[h] = W2[gn1 + h];
    }
    const float b2a = b2[d0], b2b = b2[d1];

    #pragma unroll
    for (int r = 0; r < 8; r++) {
        const int gm = m0 + ty * 8 + r;
        float s0 = 0.f, s1 = 0.f;
        #pragma unroll
        for (int j = 0; j < 2; j++) {
            float va0 = lo32(acc[r][j]) + b1a[2 * j];
            float va1 = hi32(acc[r][j]) + b1a[2 * j + 1];
            va0 = va0 >= 0.f ? va0 : NEG_SLOPE * va0;
            va1 = va1 >= 0.f ? va1 : NEG_SLOPE * va1;
            s0 += va0 * w2a[2 * j] + va1 * w2a[2 * j + 1];
            float vb0 = lo32(acc[r][j + 2]) + b1b[2 * j];
            float vb1 = hi32(acc[r][j + 2]) + b1b[2 * j + 1];
            vb0 = vb0 >= 0.f ? vb0 : NEG_SLOPE * vb0;
            vb1 = vb1 >= 0.f ? vb1 : NEG_SLOPE * vb1;
            s1 += vb0 * w2b[2 * j] + vb1 * w2b[2 * j + 1];
        }
        out2[(size_t)gm * O_ + d0] = s0 + b2a;
        out2[(size_t)gm * O_ + d1] = s1 + b2b;
    }
}

// ---------------------------------------------------------------------------
// fc head: split-K=16 into scratch, then reduce.
// ---------------------------------------------------------------------------
__global__ __launch_bounds__(256, 2)
void fc_kernel(const float* __restrict__ x, const float* __restrict__ fcW)
{
    __shared__ float As[2][BM][BK];
    __shared__ float Bs[2][BK][BN];

    const int tid = threadIdx.x;
    const int tx = tid & 15;
    const int ty = tid >> 4;
    const int m0 = blockIdx.y * BM;
    const int n0 = blockIdx.x * BN;
    const int z  = blockIdx.z;

    ull acc[8][4];
    #pragma unroll
    for (int r = 0; r < 8; r++)
        #pragma unroll
        for (int j = 0; j < 4; j++) acc[r][j] = 0ull;

    const int ar = tid >> 2;
    const int ac = (tid & 3) * 4;
    const int n_l = tid >> 1;             // 0..127
    const int kc  = (tid & 1) * 8;        // k sub-chunk
    const int n_g = n0 + n_l;
    const bool nvalid = (n_g < NC_);
    const int zk = z * (IN_ / FSPLIT);
    const float* xa0 = x + (size_t)(m0 + ar) * IN_ + zk + ac;
    const float* xa1 = x + (size_t)(m0 + ar + 64) * IN_ + zk + ac;
    const float* wp  = fcW + (size_t)n_g * IN_ + zk + kc;

    const int NT = (IN_ / FSPLIT) / BK;   // 8 ktiles

    {
        float4 pa0 = *(const float4*)(xa0);
        float4 pa1 = *(const float4*)(xa1);
        float4 pb0 = make_float4(0.f, 0.f, 0.f, 0.f), pb1 = pb0;
        if (nvalid) { pb0 = *(const float4*)(wp); pb1 = *(const float4*)(wp + 4); }
        *(float4*)&As[0][ar][ac]      = pa0;
        *(float4*)&As[0][ar + 64][ac] = pa1;
        Bs[0][kc + 0][n_l] = pb0.x; Bs[0][kc + 1][n_l] = pb0.y;
        Bs[0][kc + 2][n_l] = pb0.z; Bs[0][kc + 3][n_l] = pb0.w;
        Bs[0][kc + 4][n_l] = pb1.x; Bs[0][kc + 5][n_l] = pb1.y;
        Bs[0][kc + 6][n_l] = pb1.z; Bs[0][kc + 7][n_l] = pb1.w;
    }
    __syncthreads();

    for (int kt = 0; kt < NT; kt++) {
        const int buf = kt & 1;
        float4 pa0, pa1, pb0, pb1;
        if (kt + 1 < NT) {
            const int k0 = (kt + 1) * BK;
            pa0 = *(const float4*)(xa0 + k0);
            pa1 = *(const float4*)(xa1 + k0);
            pb0 = make_float4(0.f, 0.f, 0.f, 0.f); pb1 = pb0;
            if (nvalid) { pb0 = *(const float4*)(wp + k0); pb1 = *(const float4*)(wp + k0 + 4); }
        }
        INNER_LOOP(As[buf], Bs[buf], acc, tx, ty)
        if (kt + 1 < NT) {
            const int nb = buf ^ 1;
            *(float4*)&As[nb][ar][ac]      = pa0;
            *(float4*)&As[nb][ar + 64][ac] = pa1;
            Bs[nb][kc + 0][n_l] = pb0.x; Bs[nb][kc + 1][n_l] = pb0.y;
            Bs[nb][kc + 2][n_l] = pb0.z; Bs[nb][kc + 3][n_l] = pb0.w;
            Bs[nb][kc + 4][n_l] = pb1.x; Bs[nb][kc + 5][n_l] = pb1.y;
            Bs[nb][kc + 6][n_l] = pb1.z; Bs[nb][kc + 7][n_l] = pb1.w;
        }
        __syncthreads();
    }

    float* scr = fc_scratch + (size_t)z * (B_ * NC_);
    const int gn0 = n0 + tx * 4;
    #pragma unroll
    for (int r = 0; r < 8; r++) {
        const int gm = m0 + ty * 8 + r;
        #pragma unroll
        for (int j = 0; j < 4; j++) {
            const int gn = gn0 + (j >> 1) * 64 + (j & 1) * 2;
            float v0 = lo32(acc[r][j]);
            float v1 = hi32(acc[r][j]);
            if (gn < NC_)     scr[(size_t)gm * NC_ + gn]     = v0;
            if (gn + 1 < NC_) scr[(size_t)gm * NC_ + gn + 1] = v1;
        }
    }
}

__global__ void fc_reduce(const float* __restrict__ fcb, float* __restrict__ out1)
{
    const int i = blockIdx.x * blockDim.x + threadIdx.x;
    if (i >= B_ * NC_) return;
    const int c = i % NC_;
    float s = fcb[c];
    #pragma unroll
    for (int z = 0; z < FSPLIT; z++) s += fc_scratch[(size_t)z * (B_ * NC_) + i];
    out1[i] = s;
}

// ---------------------------------------------------------------------------
extern "C" void kernel_launch(void* const* d_in, const int* in_sizes, int n_in,
                              void* d_out, int out_size)
{
    const float* x   = (const float*)d_in[0];
    const float* fcW = (const float*)d_in[1];
    const float* fcb = (const float*)d_in[2];
    const float* W1  = (const float*)d_in[3];
    const float* b1  = (const float*)d_in[4];
    const float* W2  = (const float*)d_in[5];
    const float* b2  = (const float*)d_in[6];

    float* out1 = (float*)d_out;            // x1 [256,1000]
    float* out2 = out1 + B_ * NC_;          // x2 [256,4096]

    dim3 gdec(NDEC / BN, B_ / BM);                     // 128 x 2 = 256 CTAs
    decoder_kernel<<<gdec, 256>>>(x, W1, b1, W2, b2, out2);

    dim3 gfc((NC_ + BN - 1) / BN, B_ / BM, FSPLIT);    // 8 x 2 x 16 = 256 CTAs
    fc_kernel<<<gfc, 256>>>(x, fcW);
    fc_reduce<<<(B_ * NC_ + 255) / 256, 256>>>(fcb, out1);
}

// round 7
// speedup vs baseline: 1.0604x; 1.0604x over previous
#include <cuda_runtime.h>
#include <cstddef>
#include <cstdint>

typedef unsigned long long ull;

__device__ __forceinline__ ull ffma2(ull a, ull b, ull c) {
    ull d;
    asm("fma.rn.f32x2 %0, %1, %2, %3;" : "=l"(d) : "l"(a), "l"(b), "l"(c));
    return d;
}
__device__ __forceinline__ ull splat2(float f) {
    ull d;
    asm("mov.b64 %0, {%1, %1};" : "=l"(d) : "f"(f));
    return d;
}
__device__ __forceinline__ ull pack2(float lo, float hi) {
    ull d;
    asm("mov.b64 %0, {%1, %2};" : "=l"(d) : "f"(lo), "f"(hi));
    return d;
}
__device__ __forceinline__ float lo32(ull v) { return __uint_as_float((unsigned)v); }
__device__ __forceinline__ float hi32(ull v) { return __uint_as_float((unsigned)(v >> 32)); }

__device__ __forceinline__ void cpasync16(uint32_t dst, const void* src) {
    asm volatile("cp.async.ca.shared.global [%0], [%1], 16;" :: "r"(dst), "l"(src));
}
__device__ __forceinline__ void cpasync16p(uint32_t dst, const void* src, int srcsize) {
    asm volatile("cp.async.ca.shared.global [%0], [%1], 16, %2;" :: "r"(dst), "l"(src), "r"(srcsize));
}
__device__ __forceinline__ void cpcommit() {
    asm volatile("cp.async.commit_group;");
}
__device__ __forceinline__ void cpwait1() {
    asm volatile("cp.async.wait_group 1;");
}

#define B_    256
#define IN_   2048
#define NC_   1000
#define O_    4096
#define H_    4
#define NDEC  (O_ * H_)   // 16384
#define NEG_SLOPE 0.1f

#define BM 128
#define BN 128
#define BK 16
#define NSTG 3

#define FSPLIT 16
__device__ float fc_scratch[FSPLIT * B_ * NC_];

// Inner product over one smem ktile.
//  As_: [m][16] floats, 16B k-chunks XOR-swizzled by (m>>3)&3
//  Bs_: [k][128] plain
//  acc[r][j]: r = m row (ty*8+r); j: n = tx*4+{0,1},{2,3} / 64+tx*4+{0,1},{2,3}
__device__ __forceinline__ void inner_tile(const float (*__restrict__ As_)[BK],
                                           const float (*__restrict__ Bs_)[BN],
                                           ull acc[8][4], int tx, int ty, int swx)
{
    #pragma unroll
    for (int kb = 0; kb < BK / 2; kb++) {           // pair of k's
        const int kc = (((kb >> 1) * 4) ^ swx) + (kb & 1) * 2;
        float2 a2[8];
        #pragma unroll
        for (int r = 0; r < 8; r++)
            a2[r] = *(const float2*)&As_[ty * 8 + r][kc];
        #pragma unroll
        for (int kq = 0; kq < 2; kq++) {
            const int k = kb * 2 + kq;
            ull a[8];
            #pragma unroll
            for (int r = 0; r < 8; r++)
                a[r] = splat2(kq ? a2[r].y : a2[r].x);
            ulonglong2 b0 = *(const ulonglong2*)&Bs_[k][tx * 4];
            ulonglong2 b1 = *(const ulonglong2*)&Bs_[k][64 + tx * 4];
            ull bv[4] = {b0.x, b0.y, b1.x, b1.y};
            #pragma unroll
            for (int r = 0; r < 8; r++) {
                #pragma unroll
                for (int j = 0; j < 4; j++)
                    acc[r][j] = ffma2(a[r], bv[j], acc[r][j]);
            }
        }
    }
}

// ---------------------------------------------------------------------------
// Decoder: C[256,16384] = X @ W1r, epilogue bias+leaky+collapse -> [256,4096]
// ---------------------------------------------------------------------------
__global__ __launch_bounds__(256, 2)
void decoder_kernel(const float* __restrict__ x, const float* __restrict__ W1,
                    const float* __restrict__ b1, const float* __restrict__ W2,
                    const float* __restrict__ b2, float* __restrict__ out2)
{
    __shared__ float As[NSTG][BM][BK];
    __shared__ float Bs[NSTG][BK][BN];

    const int tid = threadIdx.x;
    const int tx = tid & 15;
    const int ty = tid >> 4;
    const int m0 = blockIdx.y * BM;
    const int n0 = blockIdx.x * BN;
    const int swx = (ty & 3) * 4;

    ull acc[8][4];
    #pragma unroll
    for (int r = 0; r < 8; r++)
        #pragma unroll
        for (int j = 0; j < 4; j++) acc[r][j] = 0ull;

    const int ar = tid >> 2;                       // 0..63
    const int tc = tid & 3;                        // source k-chunk
    const int dc = tc ^ ((ar >> 3) & 3);           // swizzled dest chunk
    const int o_l = tid & 31;
    const int e   = tid >> 5;
    const float* w1p = W1 + (size_t)(n0 / 4 + o_l) * (IN_ * H_) + e * 8;
    const float* xa0 = x + (size_t)(m0 + ar) * IN_ + tc * 4;
    const float* xa1 = x + (size_t)(m0 + ar + 64) * IN_ + tc * 4;

    uint32_t sA[NSTG][2], sB[NSTG][2];
    #pragma unroll
    for (int s = 0; s < NSTG; s++) {
        sA[s][0] = (uint32_t)__cvta_generic_to_shared(&As[s][ar][dc * 4]);
        sA[s][1] = (uint32_t)__cvta_generic_to_shared(&As[s][ar + 64][dc * 4]);
        sB[s][0] = (uint32_t)__cvta_generic_to_shared(&Bs[s][2 * e][o_l * 4]);
        sB[s][1] = (uint32_t)__cvta_generic_to_shared(&Bs[s][2 * e + 1][o_l * 4]);
    }

    const int NT = IN_ / BK;                       // 128 ktiles

    // Prologue: tile 0 -> stage 0
    cpasync16(sA[0][0], xa0);
    cpasync16(sA[0][1], xa1);
    cpasync16(sB[0][0], w1p);
    cpasync16(sB[0][1], w1p + 4);
    cpcommit();

    int cs = 0;
    for (int kt = 0; kt < NT; kt++) {
        int ns = cs + 1; if (ns == NSTG) ns = 0;
        if (kt + 1 < NT) {
            const int k0 = (kt + 1) * BK;
            cpasync16(sA[ns][0], xa0 + k0);
            cpasync16(sA[ns][1], xa1 + k0);
            const float* p0 = w1p + (size_t)k0 * H_;
            cpasync16(sB[ns][0], p0);
            cpasync16(sB[ns][1], p0 + 4);
        }
        cpcommit();
        cpwait1();
        __syncthreads();
        inner_tile(As[cs], Bs[cs], acc, tx, ty, swx);
        cs = ns;
    }

    // Epilogue: each thread owns 2 full decoders
    const int gn0 = n0 + tx * 4;
    const int gn1 = gn0 + 64;
    const int d0 = gn0 >> 2, d1 = gn1 >> 2;
    float b1a[4], w2a[4], b1b[4], w2b[4];
    #pragma unroll
    for (int h = 0; h < 4; h++) {
        b1a[h] = b1[gn0 + h]; w2a[h] = W2[gn0 + h];
        b1b[h] = b1[gn1 + h]; w2b[h] = W2[gn1 + h];
    }
    const float b2a = b2[d0], b2b = b2[d1];

    #pragma unroll
    for (int r = 0; r < 8; r++) {
        const int gm = m0 + ty * 8 + r;
        float s0 = 0.f, s1 = 0.f;
        #pragma unroll
        for (int j = 0; j < 2; j++) {
            float va0 = lo32(acc[r][j]) + b1a[2 * j];
            float va1 = hi32(acc[r][j]) + b1a[2 * j + 1];
            va0 = va0 >= 0.f ? va0 : NEG_SLOPE * va0;
            va1 = va1 >= 0.f ? va1 : NEG_SLOPE * va1;
            s0 += va0 * w2a[2 * j] + va1 * w2a[2 * j + 1];
            float vb0 = lo32(acc[r][j + 2]) + b1b[2 * j];
            float vb1 = hi32(acc[r][j + 2]) + b1b[2 * j + 1];
            vb0 = vb0 >= 0.f ? vb0 : NEG_SLOPE * vb0;
            vb1 = vb1 >= 0.f ? vb1 : NEG_SLOPE * vb1;
            s1 += vb0 * w2b[2 * j] + vb1 * w2b[2 * j + 1];
        }
        out2[(size_t)gm * O_ + d0] = s0 + b2a;
        out2[(size_t)gm * O_ + d1] = s1 + b2b;
    }
}

// ---------------------------------------------------------------------------
// fc head: split-K=16 into scratch, then reduce.
// B stored [n][k] (k contiguous, swizzled like A) so cp.async 16B works.
// ---------------------------------------------------------------------------
__global__ __launch_bounds__(256, 2)
void fc_kernel(const float* __restrict__ x, const float* __restrict__ fcW)
{
    __shared__ float As[NSTG][BM][BK];
    __shared__ float Bst[NSTG][BN][BK];

    const int tid = threadIdx.x;
    const int tx = tid & 15;
    const int ty = tid >> 4;
    const int m0 = blockIdx.y * BM;
    const int n0 = blockIdx.x * BN;
    const int z  = blockIdx.z;

    ull acc[8][4];
    #pragma unroll
    for (int r = 0; r < 8; r++)
        #pragma unroll
        for (int j = 0; j < 4; j++) acc[r][j] = 0ull;

    const int ar = tid >> 2;
    const int tc = tid & 3;
    const int dc = tc ^ ((ar >> 3) & 3);
    const int n_l = tid >> 1;                     // 0..127
    const int kc8 = (tid & 1) * 8;                // k sub-chunk base (0 or 8)
    const int n_g = n0 + n_l;
    const int bsz = (n_g < NC_) ? 16 : 0;
    const int zk = z * (IN_ / FSPLIT);
    const float* xa0 = x + (size_t)(m0 + ar) * IN_ + zk + tc * 4;
    const float* xa1 = x + (size_t)(m0 + ar + 64) * IN_ + zk + tc * 4;
    const float* wp  = fcW + (size_t)min(n_g, NC_ - 1) * IN_ + zk + kc8;

    uint32_t sA[NSTG][2], sB[NSTG][2];
    #pragma unroll
    for (int s = 0; s < NSTG; s++) {
        sA[s][0] = (uint32_t)__cvta_generic_to_shared(&As[s][ar][dc * 4]);
        sA[s][1] = (uint32_t)__cvta_generic_to_shared(&As[s][ar + 64][dc * 4]);
        const int bdc0 = (((kc8 >> 2) + 0) ^ ((n_l >> 3) & 3));
        const int bdc1 = (((kc8 >> 2) + 1) ^ ((n_l >> 3) & 3));
        sB[s][0] = (uint32_t)__cvta_generic_to_shared(&Bst[s][n_l][bdc0 * 4]);
        sB[s][1] = (uint32_t)__cvta_generic_to_shared(&Bst[s][n_l][bdc1 * 4]);
    }

    const int NT = (IN_ / FSPLIT) / BK;           // 8 ktiles

    cpasync16(sA[0][0], xa0);
    cpasync16(sA[0][1], xa1);
    cpasync16p(sB[0][0], wp, bsz);
    cpasync16p(sB[0][1], wp + 4, bsz);
    cpcommit();

    int cs = 0;
    for (int kt = 0; kt < NT; kt++) {
        int ns = cs + 1; if (ns == NSTG) ns = 0;
        if (kt + 1 < NT) {
            const int k0 = (kt + 1) * BK;
            cpasync16(sA[ns][0], xa0 + k0);
            cpasync16(sA[ns][1], xa1 + k0);
            cpasync16p(sB[ns][0], wp + k0, bsz);
            cpasync16p(sB[ns][1], wp + k0 + 4, bsz);
        }
        cpcommit();
        cpwait1();
        __syncthreads();
        {
            const float (*A_)[BK]  = As[cs];
            const float (*Bt_)[BK] = Bst[cs];
            #pragma unroll
            for (int kb = 0; kb < BK / 2; kb++) {
                float2 a2[8];
                #pragma unroll
                for (int r = 0; r < 8; r++) {
                    const int m = ty * 8 + r;
                    const int kk = (((kb >> 1) * 4) ^ (((m >> 3) & 3) * 4)) + (kb & 1) * 2;
                    a2[r] = *(const float2*)&A_[m][kk];
                }
                float2 bq[8];
                #pragma unroll
                for (int q = 0; q < 4; q++) {
                    const int nA = tx * 4 + q;
                    const int kkA = (((kb >> 1) * 4) ^ (((nA >> 3) & 3) * 4)) + (kb & 1) * 2;
                    bq[q] = *(const float2*)&Bt_[nA][kkA];
                    const int nB = 64 + tx * 4 + q;
                    const int kkB = (((kb >> 1) * 4) ^ (((nB >> 3) & 3) * 4)) + (kb & 1) * 2;
                    bq[4 + q] = *(const float2*)&Bt_[nB][kkB];
                }
                #pragma unroll
                for (int kq = 0; kq < 2; kq++) {
                    ull a[8];
                    #pragma unroll
                    for (int r = 0; r < 8; r++)
                        a[r] = splat2(kq ? a2[r].y : a2[r].x);
                    ull bv[4];
                    #pragma unroll
                    for (int j = 0; j < 4; j++)
                        bv[j] = pack2(kq ? bq[2 * j].y : bq[2 * j].x,
                                      kq ? bq[2 * j + 1].y : bq[2 * j + 1].x);
                    #pragma unroll
                    for (int r = 0; r < 8; r++) {
                        #pragma unroll
                        for (int j = 0; j < 4; j++)
                            acc[r][j] = ffma2(a[r], bv[j], acc[r][j]);
                    }
                }
            }
        }
        cs = ns;
    }

    float* scr = fc_scratch + (size_t)z * (B_ * NC_);
    const int gn0 = n0 + tx * 4;
    #pragma unroll
    for (int r = 0; r < 8; r++) {
        const int gm = m0 + ty * 8 + r;
        #pragma unroll
        for (int j = 0; j < 4; j++) {
            const int gn = gn0 + (j >> 1) * 64 + (j & 1) * 2;
            float v0 = lo32(acc[r][j]);
            float v1 = hi32(acc[r][j]);
            if (gn < NC_)     scr[(size_t)gm * NC_ + gn]     = v0;
            if (gn + 1 < NC_) scr[(size_t)gm * NC_ + gn + 1] = v1;
        }
    }
}

__global__ void fc_reduce(const float* __restrict__ fcb, float* __restrict__ out1)
{
    const int i = blockIdx.x * blockDim.x + threadIdx.x;
    if (i >= B_ * NC_) return;
    const int c = i % NC_;
    float s = fcb[c];
    #pragma unroll
    for (int z = 0; z < FSPLIT; z++) s += fc_scratch[(size_t)z * (B_ * NC_) + i];
    out1[i] = s;
}

// ---------------------------------------------------------------------------
extern "C" void kernel_launch(void* const* d_in, const int* in_sizes, int n_in,
                              void* d_out, int out_size)
{
    const float* x   = (const float*)d_in[0];
    const float* fcW = (const float*)d_in[1];
    const float* fcb = (const float*)d_in[2];
    const float* W1  = (const float*)d_in[3];
    const float* b1  = (const float*)d_in[4];
    const float* W2  = (const float*)d_in[5];
    const float* b2  = (const float*)d_in[6];

    float* out1 = (float*)d_out;            // x1 [256,1000]
    float* out2 = out1 + B_ * NC_;          // x2 [256,4096]

    dim3 gdec(NDEC / BN, B_ / BM);                     // 128 x 2 = 256 CTAs
    decoder_kernel<<<gdec, 256>>>(x, W1, b1, W2, b2, out2);

    dim3 gfc((NC_ + BN - 1) / BN, B_ / BM, FSPLIT);    // 8 x 2 x 16 = 256 CTAs
    fc_kernel<<<gfc, 256>>>(x, fcW);
    fc_reduce<<<(B_ * NC_ + 255) / 256, 256>>>(fcb, out1);
}

// round 9
// speedup vs baseline: 1.1430x; 1.0779x over previous
#include <cuda_runtime.h>
#include <cuda_bf16.h>
#include <cstdint>
#include <cstddef>

typedef unsigned long long ull;

#define BSZ   256
#define INK   2048
#define NCF   1000
#define NCP   1024
#define ODEC  4096
#define NDEC  16384
#define NEG_SLOPE 0.1f

#define BK    32
#define NKT   (INK / BK)       // 64 ktiles per pass
#define NIT   (3 * NKT)        // 192
#define STAGE_BYTES 16384      // A 8K + B 8K
#define NSTG  3

// bf16 hi/lo scratch
__device__ __nv_bfloat16 g_xh[BSZ * INK];
__device__ __nv_bfloat16 g_xl[BSZ * INK];
__device__ __nv_bfloat16 g_w1h[(size_t)NDEC * INK];
__device__ __nv_bfloat16 g_w1l[(size_t)NDEC * INK];
__device__ __nv_bfloat16 g_fwh[(size_t)NCP * INK];
__device__ __nv_bfloat16 g_fwl[(size_t)NCP * INK];

// ---------------------------------------------------------------------------
__device__ __forceinline__ uint32_t smem_u32(const void* p) {
    return (uint32_t)__cvta_generic_to_shared(p);
}
__device__ __forceinline__ void cpasync16(uint32_t dst, const void* src) {
    asm volatile("cp.async.ca.shared.global [%0], [%1], 16;" :: "r"(dst), "l"(src));
}
__device__ __forceinline__ void cpcommit() {
    asm volatile("cp.async.commit_group;");
}
__device__ __forceinline__ void ldsm4(uint32_t& r0, uint32_t& r1, uint32_t& r2,
                                      uint32_t& r3, uint32_t addr) {
    asm volatile("ldmatrix.sync.aligned.m8n8.x4.shared.b16 {%0,%1,%2,%3}, [%4];"
                 : "=r"(r0), "=r"(r1), "=r"(r2), "=r"(r3) : "r"(addr));
}
__device__ __forceinline__ void ldsm2(uint32_t& r0, uint32_t& r1, uint32_t addr) {
    asm volatile("ldmatrix.sync.aligned.m8n8.x2.shared.b16 {%0,%1}, [%2];"
                 : "=r"(r0), "=r"(r1) : "r"(addr));
}
__device__ __forceinline__ void mma16816(float* d, const uint32_t* a, const uint32_t* b) {
    asm volatile(
        "mma.sync.aligned.m16n8k16.row.col.f32.bf16.bf16.f32 "
        "{%0,%1,%2,%3}, {%4,%5,%6,%7}, {%8,%9}, {%0,%1,%2,%3};"
        : "+f"(d[0]), "+f"(d[1]), "+f"(d[2]), "+f"(d[3])
        : "r"(a[0]), "r"(a[1]), "r"(a[2]), "r"(a[3]), "r"(b[0]), "r"(b[1]));
}

// ---------------------------------------------------------------------------
// Conversion kernels: fp32 -> bf16 hi/lo split
// ---------------------------------------------------------------------------
__device__ __forceinline__ ull pk4(__nv_bfloat16 a, __nv_bfloat16 b,
                                   __nv_bfloat16 c, __nv_bfloat16 d) {
    return (ull)__bfloat16_as_ushort(a)
         | ((ull)__bfloat16_as_ushort(b) << 16)
         | ((ull)__bfloat16_as_ushort(c) << 32)
         | ((ull)__bfloat16_as_ushort(d) << 48);
}
__device__ __forceinline__ void split1(float v, __nv_bfloat16& h, __nv_bfloat16& l) {
    h = __float2bfloat16_rn(v);
    l = __float2bfloat16_rn(v - __bfloat162float(h));
}

__global__ void conv_x_kernel(const float* __restrict__ x) {
    int t = blockIdx.x * blockDim.x + threadIdx.x;   // float4 idx
    float4 v = ((const float4*)x)[t];
    __nv_bfloat16 h0,h1,h2,h3,l0,l1,l2,l3;
    split1(v.x,h0,l0); split1(v.y,h1,l1); split1(v.z,h2,l2); split1(v.w,h3,l3);
    ((ull*)g_xh)[t] = pk4(h0,h1,h2,h3);
    ((ull*)g_xl)[t] = pk4(l0,l1,l2,l3);
}

__global__ __launch_bounds__(256)
void conv_w1_kernel(const float* __restrict__ W1) {
    __shared__ __nv_bfloat16 sh[4][2048];
    __shared__ __nv_bfloat16 sl[4][2048];
    const int o = blockIdx.x;
    const int t = threadIdx.x;
    const float4* src = (const float4*)(W1 + (size_t)o * 8192);
    #pragma unroll
    for (int q = 0; q < 8; q++) {
        int i = t + q * 256;
        float4 v = src[i];
        float vv[4] = {v.x, v.y, v.z, v.w};
        #pragma unroll
        for (int h = 0; h < 4; h++) {
            __nv_bfloat16 bh, bl;
            split1(vv[h], bh, bl);
            sh[h][i] = bh;
            sl[h][i] = bl;
        }
    }
    __syncthreads();
    const int hh = t >> 6, part = t & 63;
    const uint4* s1 = (const uint4*)&sh[hh][part * 32];
    const uint4* s2 = (const uint4*)&sl[hh][part * 32];
    uint4* d1 = (uint4*)(g_w1h + (size_t)(o * 4 + hh) * INK + part * 32);
    uint4* d2 = (uint4*)(g_w1l + (size_t)(o * 4 + hh) * INK + part * 32);
    #pragma unroll
    for (int q = 0; q < 4; q++) { d1[q] = s1[q]; d2[q] = s2[q]; }
}

__global__ void conv_fcw_kernel(const float* __restrict__ fcW) {
    const int n = blockIdx.x;                // 0..1023
    const int t = threadIdx.x;
    const int base = t * 8;
    __nv_bfloat16 hb[8], lb[8];
    if (n < NCF) {
        const float4* src = (const float4*)(fcW + (size_t)n * INK + base);
        float4 a = src[0], b = src[1];
        float vv[8] = {a.x,a.y,a.z,a.w,b.x,b.y,b.z,b.w};
        #pragma unroll
        for (int j = 0; j < 8; j++) split1(vv[j], hb[j], lb[j]);
    } else {
        #pragma unroll
        for (int j = 0; j < 8; j++) { hb[j] = __float2bfloat16(0.f); lb[j] = __float2bfloat16(0.f); }
    }
    ull* dh = (ull*)(g_fwh + (size_t)n * INK + base);
    ull* dl = (ull*)(g_fwl + (size_t)n * INK + base);
    dh[0] = pk4(hb[0],hb[1],hb[2],hb[3]); dh[1] = pk4(hb[4],hb[5],hb[6],hb[7]);
    dl[0] = pk4(lb[0],lb[1],lb[2],lb[3]); dl[1] = pk4(lb[4],lb[5],lb[6],lb[7]);
}

// ---------------------------------------------------------------------------
// mma.sync GEMM: D[128m x 128n] = 3 passes (ah*bh + ah*bl + al*bh)
// smem per stage: A [128 rows x 64B] then B [128 rows x 64B], 16B chunks
// swizzled by chunk ^ ((row>>1)&3).
// ---------------------------------------------------------------------------
template<bool IS_FC>
__global__ __launch_bounds__(256, 2)
void mma_kernel(const float* __restrict__ b1, const float* __restrict__ W2,
                const float* __restrict__ b2, const float* __restrict__ fcb,
                float* __restrict__ out)
{
    __shared__ __align__(1024) char smbuf[NSTG * STAGE_BYTES];

    const int tid = threadIdx.x;
    const int lane = tid & 31;
    const int w = tid >> 5;
    const int warpm = w >> 2;       // 0..1  (64 m each)
    const int warpn = w & 3;        // 0..3  (32 n each)
    const int m0 = blockIdx.y * 128;
    const int n0 = blockIdx.x * 128;
    const uint32_t sm_u = smem_u32(smbuf);

    const __nv_bfloat16* Bh = IS_FC ? g_fwh : g_w1h;
    const __nv_bfloat16* Bl = IS_FC ? g_fwl : g_w1l;

    float acc[4][4][4];
    #pragma unroll
    for (int mi = 0; mi < 4; mi++)
        #pragma unroll
        for (int ni = 0; ni < 4; ni++)
            #pragma unroll
            for (int q = 0; q < 4; q++) acc[mi][ni][q] = 0.f;

    // --- cp.async slots: each thread 2 A-chunks + 2 B-chunks (16B) ---
    const int ldrow = tid >> 1;                 // 0..127
    const int ldc0  = (tid & 1) * 2;            // chunks c0, c0+1
    uint32_t dstA[2], dstB[2];
    size_t srcA[2], srcB[2];
    #pragma unroll
    for (int q = 0; q < 2; q++) {
        const int c = ldc0 + q;
        const int cs = c ^ ((ldrow >> 1) & 3);
        dstA[q] = (uint32_t)(ldrow * 64 + cs * 16);
        dstB[q] = (uint32_t)(8192 + ldrow * 64 + cs * 16);
        srcA[q] = (size_t)(m0 + ldrow) * INK + c * 8;
        srcB[q] = (size_t)(n0 + ldrow) * INK + c * 8;
    }

    auto do_load = [&](int stage, int it) {
        const int pass = it / NKT;
        const int kt   = it - pass * NKT;
        const __nv_bfloat16* A  = (pass < 2) ? g_xh : g_xl;
        const __nv_bfloat16* Bp = (pass == 1) ? Bl : Bh;
        const uint32_t base = sm_u + stage * STAGE_BYTES;
        const size_t koff = (size_t)kt * BK;
        #pragma unroll
        for (int q = 0; q < 2; q++) {
            cpasync16(base + dstA[q], A + srcA[q] + koff);
            cpasync16(base + dstB[q], Bp + srcB[q] + koff);
        }
    };

    // --- ldmatrix lane addressing ---
    const int arow = (lane & 7) + ((lane >> 3) & 1) * 8;  // row in 16-row tile
    const int akh  = (lane >> 4) & 1;                     // k half (0/1)
    uint32_t aRowOff[4]; int aXor[4];
    #pragma unroll
    for (int mi = 0; mi < 4; mi++) {
        const int m_r = warpm * 64 + mi * 16 + arow;
        aRowOff[mi] = (uint32_t)(m_r * 64);
        aXor[mi] = (m_r >> 1) & 3;
    }
    const int brow = lane & 7;
    const int bkh  = (lane >> 3) & 1;
    uint32_t bRowOff[4]; int bXor[4];
    #pragma unroll
    for (int ni = 0; ni < 4; ni++) {
        const int n_r = warpn * 32 + ni * 8 + brow;
        bRowOff[ni] = (uint32_t)(8192 + n_r * 64);
        bXor[ni] = (n_r >> 1) & 3;
    }

    auto compute = [&](int stage) {
        const uint32_t base = sm_u + stage * STAGE_BYTES;
        #pragma unroll
        for (int ks = 0; ks < 2; ks++) {
            uint32_t af[4][4], bf[4][2];
            #pragma unroll
            for (int mi = 0; mi < 4; mi++) {
                const uint32_t ch = (uint32_t)(((ks * 2 + akh) ^ aXor[mi]) << 4);
                ldsm4(af[mi][0], af[mi][1], af[mi][2], af[mi][3],
                      base + aRowOff[mi] + ch);
            }
            #pragma unroll
            for (int ni = 0; ni < 4; ni++) {
                const uint32_t ch = (uint32_t)((((ks * 2 + bkh) & 3) ^ bXor[ni]) << 4);
                ldsm2(bf[ni][0], bf[ni][1], base + bRowOff[ni] + ch);
            }
            #pragma unroll
            for (int mi = 0; mi < 4; mi++)
                #pragma unroll
                for (int ni = 0; ni < 4; ni++)
                    mma16816(acc[mi][ni], af[mi], bf[ni]);
        }
    };

    // --- pipeline: 2 ahead, 3 stages ---
    do_load(0, 0); cpcommit();
    do_load(1, 1); cpcommit();

    for (int it = 0; it < NIT; it++) {
        asm volatile("cp.async.wait_group 1;" ::: "memory");
        __syncthreads();
        compute(it % NSTG);
        if (it + 2 < NIT) do_load((it + 2) % NSTG, it + 2);
        cpcommit();
    }

    // --- epilogue ---
    const int gid = lane >> 2;     // 0..7
    const int tq  = lane & 3;

    if (!IS_FC) {
        #pragma unroll
        for (int ni = 0; ni < 4; ni++) {
            const int nb = n0 + warpn * 32 + ni * 8 + tq * 2;
            const float b1v0 = __ldg(&b1[nb]),     w2v0 = __ldg(&W2[nb]);
            const float b1v1 = __ldg(&b1[nb + 1]), w2v1 = __ldg(&W2[nb + 1]);
            const int dec = nb >> 2;
            const float b2v = __ldg(&b2[dec]);
            #pragma unroll
            for (int mi = 0; mi < 4; mi++) {
                #pragma unroll
                for (int h2 = 0; h2 < 2; h2++) {
                    const int gm = m0 + warpm * 64 + mi * 16 + gid + h2 * 8;
                    float v0 = acc[mi][ni][h2 * 2 + 0] + b1v0;
                    float v1 = acc[mi][ni][h2 * 2 + 1] + b1v1;
                    v0 = v0 >= 0.f ? v0 : NEG_SLOPE * v0;
                    v1 = v1 >= 0.f ? v1 : NEG_SLOPE * v1;
                    float p = v0 * w2v0 + v1 * w2v1;
                    p += __shfl_xor_sync(0xffffffffu, p, 1);
                    if ((lane & 1) == 0)
                        out[(size_t)gm * ODEC + dec] = p + b2v;
                }
            }
        }
    } else {
        #pragma unroll
        for (int ni = 0; ni < 4; ni++) {
            const int nb = n0 + warpn * 32 + ni * 8 + tq * 2;
            float fb0 = 0.f, fb1 = 0.f;
            if (nb < NCF)     fb0 = __ldg(&fcb[nb]);
            if (nb + 1 < NCF) fb1 = __ldg(&fcb[nb + 1]);
            #pragma unroll
            for (int mi = 0; mi < 4; mi++) {
                #pragma unroll
                for (int h2 = 0; h2 < 2; h2++) {
                    const int gm = m0 + warpm * 64 + mi * 16 + gid + h2 * 8;
                    if (nb < NCF)
                        out[(size_t)gm * NCF + nb]     = acc[mi][ni][h2 * 2 + 0] + fb0;
                    if (nb + 1 < NCF)
                        out[(size_t)gm * NCF + nb + 1] = acc[mi][ni][h2 * 2 + 1] + fb1;
                }
            }
        }
    }
}

// ---------------------------------------------------------------------------
extern "C" void kernel_launch(void* const* d_in, const int* in_sizes, int n_in,
                              void* d_out, int out_size)
{
    const float* x   = (const float*)d_in[0];
    const float* fcW = (const float*)d_in[1];
    const float* fcb = (const float*)d_in[2];
    const float* W1  = (const float*)d_in[3];
    const float* b1  = (const float*)d_in[4];
    const float* W2  = (const float*)d_in[5];
    const float* b2  = (const float*)d_in[6];

    float* out1 = (float*)d_out;              // x1 [256,1000]
    float* out2 = out1 + BSZ * NCF;           // x2 [256,4096]

    conv_x_kernel<<<512, 256>>>(x);
    conv_w1_kernel<<<4096, 256>>>(W1);
    conv_fcw_kernel<<<1024, 256>>>(fcW);

    mma_kernel<false><<<dim3(128, 2), 256>>>(b1, W2, b2, nullptr, out2);
    mma_kernel<true><<<dim3(8, 2), 256>>>(nullptr, nullptr, nullptr, fcb, out1);
}